// round 2
// baseline (speedup 1.0000x reference)
#include <cuda_runtime.h>
#include <cstdint>

#define H 256
#define T_STEPS 32
#define MV 4096
#define NNZ_CAP 128
#define GRU_BLOCKS 16

// ---------------- device scratch (static allocations only) ----------------
__device__ float g_seq[2][T_STEPS][H];          // summed embeddings
__device__ float g_gi[2][T_STEPS][3 * H];       // precomputed input gates
__device__ float g_h[2][H];                     // GRU hidden state (live)
__device__ float g_feats[2][T_STEPS][H];        // od / op outputs
__device__ float g_queries[T_STEPS][H];
__device__ int   g_cnt[2][MV];
__device__ int   g_cols[2][MV][NNZ_CAP];
__device__ float g_vals[2][MV][NNZ_CAP];
__device__ float g_h1[2][MV][H];
__device__ float g_S[2][MV][H];                 // adj @ h1
__device__ float g_prior[MV][H];
__device__ float g_wemb[MV];                    // logits then softmax weights
__device__ float g_wv[MV];
__device__ float g_scal[4];                     // [0] = -inter
__device__ float g_biasc[H];                    // b2_ehr - inter*b2_ddi
__device__ unsigned g_barcnt = 0;
__device__ unsigned g_bargen = 0;

// ---------------- kernel 1: embedding gather-sum ----------------
__global__ void k_embed(const int* __restrict__ dcodes, const int* __restrict__ pcodes,
                        const float* __restrict__ demb, const float* __restrict__ pemb) {
    int b = blockIdx.x;
    int m = b >> 5;           // 0 = diag, 1 = proc
    int t = b & 31;
    int tid = threadIdx.x;
    const int* codes = m ? (pcodes + t * 12) : (dcodes + t * 24);
    int L = m ? 12 : 24;
    const float* emb = m ? pemb : demb;
    float acc = 0.f;
    for (int l = 0; l < L; l++)
        acc += emb[(size_t)codes[l] * H + tid];
    g_seq[m][t][tid] = acc;
}

// ---------------- kernel 2: precompute input gates GI = seq @ wih^T + bih ----------------
__global__ void k_gi(const float* __restrict__ wd, const float* __restrict__ wp,
                     const float* __restrict__ bd, const float* __restrict__ bp) {
    int o = blockIdx.x * 8 + (threadIdx.x >> 5);   // output id 0..49151
    int lane = threadIdx.x & 31;
    int m = o / 24576;
    int rem = o - m * 24576;
    int t = rem / 768;
    int g = rem - t * 768;
    const float* wih = m ? wp : wd;
    const float* bih = m ? bp : bd;
    const float* x = g_seq[m][t];
    const float* w = wih + (size_t)g * H;
    int c0 = lane * 8;
    float4 x0 = *(const float4*)&x[c0];
    float4 x1 = *(const float4*)&x[c0 + 4];
    float4 w0 = *(const float4*)&w[c0];
    float4 w1 = *(const float4*)&w[c0 + 4];
    float acc = x0.x * w0.x + x0.y * w0.y + x0.z * w0.z + x0.w * w0.w
              + x1.x * w1.x + x1.y * w1.y + x1.z * w1.z + x1.w * w1.w;
#pragma unroll
    for (int off = 16; off; off >>= 1)
        acc += __shfl_down_sync(0xffffffffu, acc, off);
    if (lane == 0)
        g_gi[m][t][g] = acc + bih[g];
}

// ---------------- grid barrier (persistent GRU kernel) ----------------
__device__ __forceinline__ void gridbar() {
    __syncthreads();
    if (threadIdx.x == 0) {
        unsigned gen = *(volatile unsigned*)&g_bargen;
        __threadfence();
        unsigned arr = atomicAdd(&g_barcnt, 1);
        if (arr == GRU_BLOCKS - 1) {
            atomicExch(&g_barcnt, 0);
            __threadfence();
            atomicAdd(&g_bargen, 1);
        } else {
            while (*(volatile unsigned*)&g_bargen == gen) { __nanosleep(64); }
        }
        __threadfence();
    }
    __syncthreads();
}

// ---------------- kernel 3: sequential GRU (both GRUs, 16 persistent blocks) ----------------
__global__ void k_gru(const float* __restrict__ wd, const float* __restrict__ wp,
                      const float* __restrict__ bd, const float* __restrict__ bp) {
    extern __shared__ float sm[];
    float* sW = sm;                 // 96 rows x 256
    float* sH = sm + 96 * H;        // 256
    int b = blockIdx.x;
    int m = b >> 3;                 // 8 blocks per GRU
    int kbase = (b & 7) * 32;
    int tid = threadIdx.x;
    const float* whh = m ? wp : wd;
    const float* bhh = m ? bp : bd;

    // load 96 whh rows (3 gates x 32 k's) into smem
    for (int idx = tid; idx < 96 * H; idx += 256) {
        int j = idx >> 8;   // 0..95
        int c = idx & 255;
        int g = j >> 5;
        int kk = j & 31;
        sW[idx] = whh[(size_t)(g * H + kbase + kk) * H + c];
    }
    int sub = tid & 7;
    int kk = tid >> 3;               // 0..31
    int k = kbase + kk;
    float b_r = bhh[k], b_z = bhh[H + k], b_n = bhh[2 * H + k];
    if (tid < 32) __stcg(&g_h[m][kbase + tid], 0.f);
    __threadfence();

    const float* wr = sW + (0 * 32 + kk) * H;
    const float* wz = sW + (1 * 32 + kk) * H;
    const float* wn = sW + (2 * 32 + kk) * H;
    int c0 = sub * 32;

    for (int t = 0; t < T_STEPS; t++) {
        gridbar();                                   // all h writes of prev step visible
        sH[tid] = __ldcg(&g_h[m][tid]);
        __syncthreads();
        float a_r = 0.f, a_z = 0.f, a_n = 0.f;
#pragma unroll
        for (int i = 0; i < 32; i += 4) {
            float4 h4 = *(const float4*)&sH[c0 + i];
            float4 r4 = *(const float4*)&wr[c0 + i];
            float4 z4 = *(const float4*)&wz[c0 + i];
            float4 n4 = *(const float4*)&wn[c0 + i];
            a_r += r4.x * h4.x + r4.y * h4.y + r4.z * h4.z + r4.w * h4.w;
            a_z += z4.x * h4.x + z4.y * h4.y + z4.z * h4.z + z4.w * h4.w;
            a_n += n4.x * h4.x + n4.y * h4.y + n4.z * h4.z + n4.w * h4.w;
        }
#pragma unroll
        for (int off = 4; off; off >>= 1) {
            a_r += __shfl_down_sync(0xffffffffu, a_r, off, 8);
            a_z += __shfl_down_sync(0xffffffffu, a_z, off, 8);
            a_n += __shfl_down_sync(0xffffffffu, a_n, off, 8);
        }
        if (sub == 0) {
            float gi_r = g_gi[m][t][k];
            float gi_z = g_gi[m][t][H + k];
            float gi_n = g_gi[m][t][2 * H + k];
            float r = 1.f / (1.f + __expf(-(gi_r + a_r + b_r)));
            float z = 1.f / (1.f + __expf(-(gi_z + a_z + b_z)));
            float n = tanhf(gi_n + r * (a_n + b_n));
            float h2 = (1.f - z) * n + z * sH[k];
            __stcg(&g_h[m][k], h2);
            g_feats[m][t][k] = h2;
        }
        __threadfence();
    }
}

// ---------------- kernel 4: queries = relu(feats) @ q_w + q_b ----------------
__global__ void k_queries(const float* __restrict__ qw, const float* __restrict__ qb) {
    int t = blockIdx.x;
    int tid = threadIdx.x;
    __shared__ float f[2 * H];
    f[tid] = fmaxf(g_feats[0][t][tid], 0.f);
    f[H + tid] = fmaxf(g_feats[1][t][tid], 0.f);
    __syncthreads();
    float acc = qb[tid];
#pragma unroll 8
    for (int k2 = 0; k2 < 2 * H; k2++)
        acc += f[k2] * qw[(size_t)k2 * H + tid];
    g_queries[t][tid] = acc;
}

// ---------------- kernel 5: CSR build (deterministic compaction) ----------------
__global__ void k_csr(const float* __restrict__ adj_e, const float* __restrict__ adj_d) {
    int b = blockIdx.x;
    int m = b >> 12;
    int r = b & 4095;
    const float* row = (m ? adj_d : adj_e) + (size_t)r * MV;
    int tid = threadIdx.x;
    __shared__ int scnt[256];
    float v[16];
    const float4* r4 = (const float4*)(row + tid * 16);
#pragma unroll
    for (int i = 0; i < 4; i++) {
        float4 x = r4[i];
        v[4 * i + 0] = x.x; v[4 * i + 1] = x.y; v[4 * i + 2] = x.z; v[4 * i + 3] = x.w;
    }
    int c = 0;
#pragma unroll
    for (int i = 0; i < 16; i++) c += (v[i] != 0.f);
    scnt[tid] = c;
    __syncthreads();
    int val = c;
    for (int off = 1; off < 256; off <<= 1) {
        int add = (tid >= off) ? scnt[tid - off] : 0;
        __syncthreads();
        val += add;
        scnt[tid] = val;
        __syncthreads();
    }
    int total = scnt[255];
    int idx = val - c;   // exclusive prefix
#pragma unroll
    for (int i = 0; i < 16; i++) {
        if (v[i] != 0.f) {
            if (idx < NNZ_CAP) {
                g_cols[m][r][idx] = tid * 16 + i;
                g_vals[m][r][idx] = v[i];
            }
            idx++;
        }
    }
    if (tid == 0)
        g_cnt[m][r] = total < NNZ_CAP ? total : NNZ_CAP;
}

// ---------------- kernel 6: SpMM (phase 0: relu(adj@w1+b1); phase 1: adj@h1) ----------------
template <int PHASE>
__global__ void k_spmm(const float* __restrict__ X0, const float* __restrict__ X1,
                       const float* __restrict__ b0, const float* __restrict__ b1) {
    int b = blockIdx.x;
    int m = b >> 12;
    int r = b & 4095;
    int tid = threadIdx.x;
    __shared__ int sc[NNZ_CAP];
    __shared__ float sv[NNZ_CAP];
    int nnz = g_cnt[m][r];
    if (tid < nnz) {
        sc[tid] = g_cols[m][r][tid];
        sv[tid] = g_vals[m][r][tid];
    }
    __syncthreads();
    const float* X;
    if (PHASE == 0) X = m ? X1 : X0;
    else            X = &g_h1[m][0][0];
    float acc = 0.f;
    for (int j = 0; j < nnz; j++)
        acc += sv[j] * X[(size_t)sc[j] * H + tid];
    if (PHASE == 0) {
        const float* bb = m ? b1 : b0;
        acc = fmaxf(acc + bb[tid], 0.f);
        g_h1[m][r][tid] = acc;
    } else {
        g_S[m][r][tid] = acc;
    }
}

// ---------------- kernel 7: small prep (-inter, combined bias) ----------------
__global__ void k_prep(const float* __restrict__ inter, const float* __restrict__ b2e,
                       const float* __restrict__ b2d) {
    float iv = inter[0];
    if (threadIdx.x == 0) g_scal[0] = -iv;
    g_biasc[threadIdx.x] = b2e[threadIdx.x] - iv * b2d[threadIdx.x];
}

// ---------------- kernel 8/12: fused two-pair dense matmul ----------------
// MODE 0: g_prior = g_S[0]@W0 + (-inter)*g_S[1]@W1 + g_biasc
// MODE 1: C = diag(w_emb)*g_prior@W0 + diag(wv)*g_prior@W1 + bias
template <int MODE>
__global__ void k_mm2(const float* __restrict__ W0, const float* __restrict__ W1,
                      const float* __restrict__ biasx, float* __restrict__ Cx) {
    __shared__ float As[64][17];
    __shared__ float Ws[16][64];
    int tid = threadIdx.x;
    int row0 = blockIdx.y * 64;
    int col0 = blockIdx.x * 64;
    int tm = tid >> 4, tn = tid & 15;
    int lr = tid >> 2;            // A-load row 0..63
    int lc4 = (tid & 3) * 4;      // A-load k offset
    int wk = tid >> 4;            // W-load k 0..15
    int wn4 = (tid & 15) * 4;     // W-load n offset
    float acc[4][4] = {};

    for (int p = 0; p < 2; p++) {
        const float* A = (MODE == 0) ? &g_S[p][0][0] : &g_prior[0][0];
        const float* W = p ? W1 : W0;
        float rs;
        if (MODE == 0) rs = p ? g_scal[0] : 1.f;
        else           rs = p ? g_wv[row0 + lr] : g_wemb[row0 + lr];
        for (int kc = 0; kc < H; kc += 16) {
            __syncthreads();
            float4 av = *(const float4*)&A[(size_t)(row0 + lr) * H + kc + lc4];
            As[lr][lc4 + 0] = av.x * rs;
            As[lr][lc4 + 1] = av.y * rs;
            As[lr][lc4 + 2] = av.z * rs;
            As[lr][lc4 + 3] = av.w * rs;
            *(float4*)&Ws[wk][wn4] = *(const float4*)&W[(size_t)(kc + wk) * H + col0 + wn4];
            __syncthreads();
#pragma unroll
            for (int kkk = 0; kkk < 16; kkk++) {
                float4 wv4 = *(const float4*)&Ws[kkk][tn * 4];
#pragma unroll
                for (int i = 0; i < 4; i++) {
                    float a = As[tm * 4 + i][kkk];
                    acc[i][0] += a * wv4.x;
                    acc[i][1] += a * wv4.y;
                    acc[i][2] += a * wv4.z;
                    acc[i][3] += a * wv4.w;
                }
            }
        }
    }
    const float* bias = (MODE == 0) ? g_biasc : biasx;
    float* C = (MODE == 0) ? &g_prior[0][0] : Cx;
    float4 bv = *(const float4*)&bias[col0 + tn * 4];
#pragma unroll
    for (int i = 0; i < 4; i++) {
        int rr = row0 + tm * 4 + i;
        float4 o;
        o.x = acc[i][0] + bv.x;
        o.y = acc[i][1] + bv.y;
        o.z = acc[i][2] + bv.z;
        o.w = acc[i][3] + bv.w;
        *(float4*)&C[(size_t)rr * H + col0 + tn * 4] = o;
    }
}

// ---------------- kernel 9: logits = prior @ query ----------------
__global__ void k_logits() {
    int row = blockIdx.x * 8 + (threadIdx.x >> 5);
    int lane = threadIdx.x & 31;
    const float* pr = g_prior[row];
    float acc = 0.f;
#pragma unroll
    for (int i = 0; i < 8; i++)
        acc += pr[lane + 32 * i] * g_queries[T_STEPS - 1][lane + 32 * i];
#pragma unroll
    for (int off = 16; off; off >>= 1)
        acc += __shfl_down_sync(0xffffffffu, acc, off);
    if (lane == 0) g_wemb[row] = acc;
}

// ---------------- kernel 10: softmax over 4096 logits ----------------
__global__ void k_softmax() {
    int tid = threadIdx.x;  // 1024
    __shared__ float red[32];
    __shared__ float bval;
    float v[4];
#pragma unroll
    for (int i = 0; i < 4; i++) v[i] = g_wemb[tid + 1024 * i];
    float mx = fmaxf(fmaxf(v[0], v[1]), fmaxf(v[2], v[3]));
#pragma unroll
    for (int off = 16; off; off >>= 1)
        mx = fmaxf(mx, __shfl_down_sync(0xffffffffu, mx, off));
    if ((tid & 31) == 0) red[tid >> 5] = mx;
    __syncthreads();
    if (tid < 32) {
        float m2 = red[tid];
#pragma unroll
        for (int off = 16; off; off >>= 1)
            m2 = fmaxf(m2, __shfl_down_sync(0xffffffffu, m2, off));
        if (tid == 0) bval = m2;
    }
    __syncthreads();
    mx = bval;
    float s = 0.f;
#pragma unroll
    for (int i = 0; i < 4; i++) { v[i] = __expf(v[i] - mx); s += v[i]; }
#pragma unroll
    for (int off = 16; off; off >>= 1)
        s += __shfl_down_sync(0xffffffffu, s, off);
    __syncthreads();
    if ((tid & 31) == 0) red[tid >> 5] = s;
    __syncthreads();
    if (tid < 32) {
        float s2 = red[tid];
#pragma unroll
        for (int off = 16; off; off >>= 1)
            s2 += __shfl_down_sync(0xffffffffu, s2, off);
        if (tid == 0) bval = s2;
    }
    __syncthreads();
    float inv = 1.f / bval;
#pragma unroll
    for (int i = 0; i < 4; i++) g_wemb[tid + 1024 * i] = v[i] * inv;
}

// ---------------- kernel 11: visit attention + history scatter ----------------
__global__ void k_visit(const int* __restrict__ med) {
    int tid = threadIdx.x;  // 1024
    __shared__ float lv[32];
    __shared__ float vw[31];
    int w = tid >> 5, lane = tid & 31;
    if (w < 31) {
        float acc = 0.f;
#pragma unroll
        for (int i = 0; i < 8; i++)
            acc += g_queries[T_STEPS - 1][lane + 32 * i] * g_queries[w][lane + 32 * i];
#pragma unroll
        for (int off = 16; off; off >>= 1)
            acc += __shfl_down_sync(0xffffffffu, acc, off);
        if (lane == 0) lv[w] = acc;
    }
    __syncthreads();
    if (tid == 0) {
        float mx = -1e30f;
        for (int t = 0; t < 31; t++) mx = fmaxf(mx, lv[t]);
        float s = 0.f;
        for (int t = 0; t < 31; t++) { float e = __expf(lv[t] - mx); vw[t] = e; s += e; }
        float inv = 1.f / s;
        for (int t = 0; t < 31; t++) vw[t] *= inv;
    }
    for (int i = tid; i < MV; i += 1024) g_wv[i] = 0.f;
    __syncthreads();
    if (tid < 31 * 20) {
        int t = tid / 20, l = tid % 20;
        int c = med[t * 20 + l];
        bool dup = false;
        for (int l2 = 0; l2 < l; l2++)
            if (med[t * 20 + l2] == c) dup = true;
        if (!dup) atomicAdd(&g_wv[c], vw[t]);
    }
}

// ---------------- launch ----------------
extern "C" void kernel_launch(void* const* d_in, const int* in_sizes, int n_in,
                              void* d_out, int out_size) {
    const int*   diag_codes = (const int*)d_in[0];
    const int*   proc_codes = (const int*)d_in[1];
    const int*   med_codes  = (const int*)d_in[2];
    const float* diag_emb   = (const float*)d_in[3];
    const float* proc_emb   = (const float*)d_in[4];
    const float* gd_wih     = (const float*)d_in[5];
    const float* gd_whh     = (const float*)d_in[6];
    const float* gd_bih     = (const float*)d_in[7];
    const float* gd_bhh     = (const float*)d_in[8];
    const float* gp_wih     = (const float*)d_in[9];
    const float* gp_whh     = (const float*)d_in[10];
    const float* gp_bih     = (const float*)d_in[11];
    const float* gp_bhh     = (const float*)d_in[12];
    const float* q_w        = (const float*)d_in[13];
    const float* q_b        = (const float*)d_in[14];
    const float* adj_ehr    = (const float*)d_in[15];
    const float* adj_ddi    = (const float*)d_in[16];
    const float* w1_ehr     = (const float*)d_in[17];
    const float* b1_ehr     = (const float*)d_in[18];
    const float* w2_ehr     = (const float*)d_in[19];
    const float* b2_ehr     = (const float*)d_in[20];
    const float* w1_ddi     = (const float*)d_in[21];
    const float* b1_ddi     = (const float*)d_in[22];
    const float* w2_ddi     = (const float*)d_in[23];
    const float* b2_ddi     = (const float*)d_in[24];
    const float* inter      = (const float*)d_in[25];
    const float* proj_w     = (const float*)d_in[26];
    const float* proj_b     = (const float*)d_in[27];
    float* out = (float*)d_out;

    static_assert(96 * H * 4 + H * 4 == 99328, "smem");
    cudaFuncSetAttribute(k_gru, cudaFuncAttributeMaxDynamicSharedMemorySize, 99328);

    // front-end (GRU path)
    k_embed<<<64, 256>>>(diag_codes, proc_codes, diag_emb, proc_emb);
    k_gi<<<6144, 256>>>(gd_wih, gp_wih, gd_bih, gp_bih);
    k_gru<<<GRU_BLOCKS, 256, 99328>>>(gd_whh, gp_whh, gd_bhh, gp_bhh);
    k_queries<<<32, 256>>>(q_w, q_b);

    // GCN path (sparse)
    k_csr<<<2 * MV, 256>>>(adj_ehr, adj_ddi);
    k_spmm<0><<<2 * MV, 256>>>(w1_ehr, w1_ddi, b1_ehr, b1_ddi);
    k_spmm<1><<<2 * MV, 256>>>(nullptr, nullptr, nullptr, nullptr);
    k_prep<<<1, 256>>>(inter, b2_ehr, b2_ddi);
    k_mm2<0><<<dim3(4, 64), 256>>>(w2_ehr, w2_ddi, nullptr, nullptr);

    // attention + output
    k_logits<<<512, 256>>>();
    k_softmax<<<1, 1024>>>();
    k_visit<<<1, 1024>>>(med_codes);
    // second half of proj_w (rows 256..511 of the (512,256) matrix) = +H*H elements
    k_mm2<1><<<dim3(4, 64), 256>>>(proj_w, proj_w + H * H, proj_b, out);
}

// round 6
// speedup vs baseline: 1.6561x; 1.6561x over previous
#include <cuda_runtime.h>
#include <cstdint>

#define H 256
#define T_STEPS 32
#define MV 4096
#define NNZ_CAP 128

// ---------------- device scratch (static allocations only) ----------------
__device__ float g_gi[2][T_STEPS][3 * H];       // precomputed input gates
__device__ float g_feats[2][T_STEPS][H];        // od / op outputs
__device__ float g_queries[T_STEPS][H];
__device__ int   g_cnt[2][MV];
__device__ int   g_cols[2][MV][NNZ_CAP];
__device__ float g_vals[2][MV][NNZ_CAP];
__device__ float g_h1[2][MV][H];
__device__ float g_S[2][MV][H];                 // adj @ h1
__device__ float g_prior[MV][H];
__device__ float g_wemb[MV];                    // logits then softmax weights
__device__ float g_wv[MV];
__device__ float g_scal[4];                     // [0] = -inter
__device__ float g_biasc[H];                    // b2_ehr - inter*b2_ddi

// ---------------- kernel 1 (fused embed + input-gate GEMV) ----------------
// 64 blocks = (m, t). Phase A: embedding gather-sum into smem.
// Phase B: 8 warps compute the 768 gate outputs gi = x @ wih^T + bih.
__global__ void k_gie(const int* __restrict__ dcodes, const int* __restrict__ pcodes,
                      const float* __restrict__ demb, const float* __restrict__ pemb,
                      const float* __restrict__ wd, const float* __restrict__ wp,
                      const float* __restrict__ bd, const float* __restrict__ bp) {
    int b = blockIdx.x;
    int m = b >> 5;           // 0 = diag, 1 = proc
    int t = b & 31;
    int tid = threadIdx.x;
    __shared__ float x[H];
    const int* codes = m ? (pcodes + t * 12) : (dcodes + t * 24);
    int L = m ? 12 : 24;
    const float* emb = m ? pemb : demb;
    float acc = 0.f;
    for (int l = 0; l < L; l++)
        acc += emb[(size_t)codes[l] * H + tid];
    x[tid] = acc;
    __syncthreads();

    int wid = tid >> 5, lane = tid & 31;
    const float* wih = m ? wp : wd;
    const float* bih = m ? bp : bd;
    int c0 = lane * 8;
    float4 x0 = *(const float4*)&x[c0];
    float4 x1 = *(const float4*)&x[c0 + 4];
    for (int g = wid; g < 3 * H; g += 8) {
        const float* w = wih + (size_t)g * H;
        float4 w0 = *(const float4*)&w[c0];
        float4 w1 = *(const float4*)&w[c0 + 4];
        float a = x0.x * w0.x + x0.y * w0.y + x0.z * w0.z + x0.w * w0.w
                + x1.x * w1.x + x1.y * w1.y + x1.z * w1.z + x1.w * w1.w;
#pragma unroll
        for (int off = 16; off; off >>= 1)
            a += __shfl_down_sync(0xffffffffu, a, off);
        if (lane == 0)
            g_gi[m][t][g] = a + bih[g];
    }
}

// ---------------- DSMEM / cluster helpers ----------------
__device__ __forceinline__ void dsmem_store_f32(uint32_t local_addr, uint32_t rank, float v) {
    uint32_t remote;
    asm volatile("mapa.shared::cluster.u32 %0, %1, %2;" : "=r"(remote) : "r"(local_addr), "r"(rank));
    asm volatile("st.shared::cluster.f32 [%0], %1;" :: "r"(remote), "f"(v) : "memory");
}
__device__ __forceinline__ void cluster_sync_all() {
    asm volatile("barrier.cluster.arrive.aligned;" ::: "memory");
    asm volatile("barrier.cluster.wait.aligned;" ::: "memory");
}

// ---------------- kernel 2 (FUSED): GRU clusters + CSR build + SpMM-0 + prep ----------------
// grid = 8208 blocks, cluster 8.
//   blocks 0..15    : 2 GRU clusters (8 CTAs each), weights in registers, h via DSMEM
//   blocks 16..8207 : CSR row compaction -> smem -> (a) CSR to gmem for SpMM-1
//                     (b) h1[r] = relu(adj_row @ w1 + b1) directly from smem nnz list
__global__ void __cluster_dims__(8, 1, 1) k_fused(
        const float* __restrict__ wd, const float* __restrict__ wp,
        const float* __restrict__ bd, const float* __restrict__ bp,
        const float* __restrict__ adj_e, const float* __restrict__ adj_d,
        const float* __restrict__ w1e, const float* __restrict__ w1d,
        const float* __restrict__ b1e, const float* __restrict__ b1d,
        const float* __restrict__ inter, const float* __restrict__ b2e,
        const float* __restrict__ b2d) {
    __shared__ float sH[2][H];          // GRU double-buffered hidden state
    __shared__ int   scnt[256];         // CSR scan
    __shared__ int   sc[NNZ_CAP];
    __shared__ float sv[NNZ_CAP];
    int b = blockIdx.x;
    int tid = threadIdx.x;

    if (b < 16) {
        // ================= GRU path =================
        int m = b >> 3;                 // cluster id = GRU id
        int kbase = (b & 7) * 32;
        const float* whh = m ? wp : wd;
        const float* bhh = m ? bp : bd;
        int sub = tid & 7;
        int kk = tid >> 3;              // 0..31
        int k = kbase + kk;
        int c0 = sub * 32;

        // per-thread weights: rows (g*H + k), cols c0..c0+31, g = r/z/n
        float wreg[96];
#pragma unroll
        for (int g = 0; g < 3; g++) {
            const float* src = whh + (size_t)(g * H + k) * H + c0;
#pragma unroll
            for (int i = 0; i < 32; i += 4) {
                float4 w4 = *(const float4*)&src[i];
                wreg[g * 32 + i + 0] = w4.x;
                wreg[g * 32 + i + 1] = w4.y;
                wreg[g * 32 + i + 2] = w4.z;
                wreg[g * 32 + i + 3] = w4.w;
            }
        }
        float b_r = bhh[k], b_z = bhh[H + k], b_n = bhh[2 * H + k];
        if (tid < H) sH[0][tid] = 0.f;  // h_{-1} = 0
        __syncthreads();
        uint32_t sh_base = (uint32_t)__cvta_generic_to_shared(&sH[0][0]);

        for (int t = 0; t < T_STEPS; t++) {
            const float* hb = sH[t & 1];
            float a_r = 0.f, a_z = 0.f, a_n = 0.f;
#pragma unroll
            for (int i = 0; i < 32; i += 4) {
                float4 h4 = *(const float4*)&hb[c0 + i];
                a_r += wreg[i] * h4.x + wreg[i + 1] * h4.y + wreg[i + 2] * h4.z + wreg[i + 3] * h4.w;
                a_z += wreg[32 + i] * h4.x + wreg[33 + i] * h4.y + wreg[34 + i] * h4.z + wreg[35 + i] * h4.w;
                a_n += wreg[64 + i] * h4.x + wreg[65 + i] * h4.y + wreg[66 + i] * h4.z + wreg[67 + i] * h4.w;
            }
#pragma unroll
            for (int off = 4; off; off >>= 1) {
                a_r += __shfl_down_sync(0xffffffffu, a_r, off, 8);
                a_z += __shfl_down_sync(0xffffffffu, a_z, off, 8);
                a_n += __shfl_down_sync(0xffffffffu, a_n, off, 8);
            }
            if (sub == 0) {
                float gi_r = g_gi[m][t][k];
                float gi_z = g_gi[m][t][H + k];
                float gi_n = g_gi[m][t][2 * H + k];
                float r = 1.f / (1.f + __expf(-(gi_r + a_r + b_r)));
                float z = 1.f / (1.f + __expf(-(gi_z + a_z + b_z)));
                float n = tanhf(gi_n + r * (a_n + b_n));
                float h2 = (1.f - z) * n + z * hb[k];
                g_feats[m][t][k] = h2;
                uint32_t dst = sh_base + (uint32_t)((((t & 1) ^ 1) * H + k) * 4);
#pragma unroll
                for (uint32_t r8 = 0; r8 < 8; r8++)
                    dsmem_store_f32(dst, r8, h2);
            }
            cluster_sync_all();
        }
        return;
    }

    // ================= CSR + SpMM-0 path =================
    int bb = b - 16;
    if (bb == 0) {                       // folded prep (cheap)
        float iv = inter[0];
        if (tid == 0) g_scal[0] = -iv;
        g_biasc[tid] = b2e[tid] - iv * b2d[tid];
    }
    int m = bb >> 12;
    int r = bb & 4095;
    const float* row = (m ? adj_d : adj_e) + (size_t)r * MV;
    float v[16];
    const float4* r4 = (const float4*)(row + tid * 16);
#pragma unroll
    for (int i = 0; i < 4; i++) {
        float4 x = r4[i];
        v[4 * i + 0] = x.x; v[4 * i + 1] = x.y; v[4 * i + 2] = x.z; v[4 * i + 3] = x.w;
    }
    int c = 0;
#pragma unroll
    for (int i = 0; i < 16; i++) c += (v[i] != 0.f);
    scnt[tid] = c;
    __syncthreads();
    int val = c;
    for (int off = 1; off < 256; off <<= 1) {
        int add = (tid >= off) ? scnt[tid - off] : 0;
        __syncthreads();
        val += add;
        scnt[tid] = val;
        __syncthreads();
    }
    int total = scnt[255];
    int idx = val - c;   // exclusive prefix
#pragma unroll
    for (int i = 0; i < 16; i++) {
        if (v[i] != 0.f) {
            if (idx < NNZ_CAP) {
                sc[idx] = tid * 16 + i;
                sv[idx] = v[i];
                g_cols[m][r][idx] = tid * 16 + i;   // for SpMM-1
                g_vals[m][r][idx] = v[i];
            }
            idx++;
        }
    }
    int nnz = total < NNZ_CAP ? total : NNZ_CAP;
    if (tid == 0) g_cnt[m][r] = nnz;
    __syncthreads();

    // SpMM-0: h1[r] = relu(sum_j sv[j] * w1[sc[j]][:] + b1)
    const float* W1 = m ? w1d : w1e;
    const float* B1 = m ? b1d : b1e;
    float acc = 0.f;
    for (int j = 0; j < nnz; j++)
        acc += sv[j] * W1[(size_t)sc[j] * H + tid];
    g_h1[m][r][tid] = fmaxf(acc + B1[tid], 0.f);
}

// ---------------- kernel 3 (fused SpMM-1 + queries + wemb-zero) ----------------
// blocks 0..8191: S = adj @ h1 (block 0..15 also zero g_wemb for the logits atomics)
// blocks 8192..8319: queries = relu(feats) @ q_w + q_b
__global__ void k_sq(const float* __restrict__ qw, const float* __restrict__ qb) {
    int b = blockIdx.x;
    int tid = threadIdx.x;
    if (b < 2 * MV) {
        if (b < 16) g_wemb[b * 256 + tid] = 0.f;   // zero logits accumulator
        int m = b >> 12;
        int r = b & 4095;
        __shared__ int sc[NNZ_CAP];
        __shared__ float sv[NNZ_CAP];
        int nnz = g_cnt[m][r];
        if (tid < nnz) {
            sc[tid] = g_cols[m][r][tid];
            sv[tid] = g_vals[m][r][tid];
        }
        __syncthreads();
        const float* X = &g_h1[m][0][0];
        float acc = 0.f;
        for (int j = 0; j < nnz; j++)
            acc += sv[j] * X[(size_t)sc[j] * H + tid];
        g_S[m][r][tid] = acc;
    } else {
        int q2 = b - 2 * MV;     // 0..127
        int t = q2 >> 2;
        int c0 = (q2 & 3) * 64;
        __shared__ float f[2 * H];
        __shared__ float part[4][64];
        for (int i = tid; i < H; i += 256) {
            f[i] = fmaxf(g_feats[0][t][i], 0.f);
            f[H + i] = fmaxf(g_feats[1][t][i], 0.f);
        }
        __syncthreads();
        int q = tid >> 6;        // k-quarter 0..3 (each 128 k's)
        int c = tid & 63;
        const float* W = qw + (size_t)(q * 128) * H + c0 + c;
        float acc = 0.f;
#pragma unroll 8
        for (int k2 = 0; k2 < 128; k2++)
            acc += f[q * 128 + k2] * W[(size_t)k2 * H];
        part[q][c] = acc;
        __syncthreads();
        if (q == 0)
            g_queries[t][c0 + c] = part[0][c] + part[1][c] + part[2][c] + part[3][c] + qb[c0 + c];
    }
}

// ---------------- kernel 4/6: fused two-pair dense matmul ----------------
// MODE 0: g_prior = g_S[0]@W0 + (-inter)*g_S[1]@W1 + g_biasc ; ALSO accumulates
//         logits g_wemb[r] += prior_tile_row . query_slice via half-warp reduce + atomicAdd.
// MODE 1: C = diag(w_emb)*g_prior@W0 + diag(wv)*g_prior@W1 + bias
template <int MODE>
__global__ void k_mm2(const float* __restrict__ W0, const float* __restrict__ W1,
                      const float* __restrict__ biasx, float* __restrict__ Cx) {
    __shared__ float AsT[16][72];   // [k][row]
    __shared__ float Ws[16][68];
    int tid = threadIdx.x;
    int row0 = blockIdx.y * 64;
    int col0 = blockIdx.x * 64;
    int tm = tid >> 4, tn = tid & 15;
    int lr = tid >> 2;            // A-load row 0..63
    int lc4 = (tid & 3) * 4;      // A-load k offset
    int wk = tid >> 4;            // W-load k 0..15
    int wn4 = (tid & 15) * 4;     // W-load n offset
    float acc[4][4] = {};

    for (int p = 0; p < 2; p++) {
        const float* A = (MODE == 0) ? &g_S[p][0][0] : &g_prior[0][0];
        const float* W = p ? W1 : W0;
        float rs;
        if (MODE == 0) rs = p ? g_scal[0] : 1.f;
        else           rs = p ? g_wv[row0 + lr] : g_wemb[row0 + lr];
        for (int kc = 0; kc < H; kc += 16) {
            __syncthreads();
            float4 av = *(const float4*)&A[(size_t)(row0 + lr) * H + kc + lc4];
            AsT[lc4 + 0][lr] = av.x * rs;
            AsT[lc4 + 1][lr] = av.y * rs;
            AsT[lc4 + 2][lr] = av.z * rs;
            AsT[lc4 + 3][lr] = av.w * rs;
            *(float4*)&Ws[wk][wn4] = *(const float4*)&W[(size_t)(kc + wk) * H + col0 + wn4];
            __syncthreads();
#pragma unroll
            for (int kkk = 0; kkk < 16; kkk++) {
                float4 a4 = *(const float4*)&AsT[kkk][tm * 4];
                float4 w4 = *(const float4*)&Ws[kkk][tn * 4];
                acc[0][0] += a4.x * w4.x; acc[0][1] += a4.x * w4.y;
                acc[0][2] += a4.x * w4.z; acc[0][3] += a4.x * w4.w;
                acc[1][0] += a4.y * w4.x; acc[1][1] += a4.y * w4.y;
                acc[1][2] += a4.y * w4.z; acc[1][3] += a4.y * w4.w;
                acc[2][0] += a4.z * w4.x; acc[2][1] += a4.z * w4.y;
                acc[2][2] += a4.z * w4.z; acc[2][3] += a4.z * w4.w;
                acc[3][0] += a4.w * w4.x; acc[3][1] += a4.w * w4.y;
                acc[3][2] += a4.w * w4.z; acc[3][3] += a4.w * w4.w;
            }
        }
    }
    const float* bias = (MODE == 0) ? g_biasc : biasx;
    float* C = (MODE == 0) ? &g_prior[0][0] : Cx;
    float4 bv = *(const float4*)&bias[col0 + tn * 4];
    float4 qv;
    if (MODE == 0) qv = *(const float4*)&g_queries[T_STEPS - 1][col0 + tn * 4];
#pragma unroll
    for (int i = 0; i < 4; i++) {
        int rr = row0 + tm * 4 + i;
        float4 o;
        o.x = acc[i][0] + bv.x;
        o.y = acc[i][1] + bv.y;
        o.z = acc[i][2] + bv.z;
        o.w = acc[i][3] + bv.w;
        *(float4*)&C[(size_t)rr * H + col0 + tn * 4] = o;
        if (MODE == 0) {
            // partial logit: prior_row . query over this block's 64 cols
            float s = o.x * qv.x + o.y * qv.y + o.z * qv.z + o.w * qv.w;
#pragma unroll
            for (int off = 8; off; off >>= 1)
                s += __shfl_down_sync(0xffffffffu, s, off, 16);
            if (tn == 0) atomicAdd(&g_wemb[rr], s);
        }
    }
}

// ---------------- kernel 5: fused tail (block 0: softmax; block 1: visit attn) ----------------
__global__ void k_tail(const int* __restrict__ med) {
    int tid = threadIdx.x;  // 1024
    if (blockIdx.x == 0) {
        __shared__ float red[32];
        __shared__ float bval;
        float v[4];
#pragma unroll
        for (int i = 0; i < 4; i++) v[i] = g_wemb[tid + 1024 * i];
        float mx = fmaxf(fmaxf(v[0], v[1]), fmaxf(v[2], v[3]));
#pragma unroll
        for (int off = 16; off; off >>= 1)
            mx = fmaxf(mx, __shfl_down_sync(0xffffffffu, mx, off));
        if ((tid & 31) == 0) red[tid >> 5] = mx;
        __syncthreads();
        if (tid < 32) {
            float m2 = red[tid];
#pragma unroll
            for (int off = 16; off; off >>= 1)
                m2 = fmaxf(m2, __shfl_down_sync(0xffffffffu, m2, off));
            if (tid == 0) bval = m2;
        }
        __syncthreads();
        mx = bval;
        float s = 0.f;
#pragma unroll
        for (int i = 0; i < 4; i++) { v[i] = __expf(v[i] - mx); s += v[i]; }
#pragma unroll
        for (int off = 16; off; off >>= 1)
            s += __shfl_down_sync(0xffffffffu, s, off);
        __syncthreads();
        if ((tid & 31) == 0) red[tid >> 5] = s;
        __syncthreads();
        if (tid < 32) {
            float s2 = red[tid];
#pragma unroll
            for (int off = 16; off; off >>= 1)
                s2 += __shfl_down_sync(0xffffffffu, s2, off);
            if (tid == 0) bval = s2;
        }
        __syncthreads();
        float inv = 1.f / bval;
#pragma unroll
        for (int i = 0; i < 4; i++) g_wemb[tid + 1024 * i] = v[i] * inv;
    } else {
        __shared__ float lv[32];
        __shared__ float vw[31];
        int w = tid >> 5, lane = tid & 31;
        if (w < 31) {
            float acc = 0.f;
#pragma unroll
            for (int i = 0; i < 8; i++)
                acc += g_queries[T_STEPS - 1][lane + 32 * i] * g_queries[w][lane + 32 * i];
#pragma unroll
            for (int off = 16; off; off >>= 1)
                acc += __shfl_down_sync(0xffffffffu, acc, off);
            if (lane == 0) lv[w] = acc;
        }
        __syncthreads();
        if (tid == 0) {
            float mx = -1e30f;
            for (int t = 0; t < 31; t++) mx = fmaxf(mx, lv[t]);
            float s = 0.f;
            for (int t = 0; t < 31; t++) { float e = __expf(lv[t] - mx); vw[t] = e; s += e; }
            float inv = 1.f / s;
            for (int t = 0; t < 31; t++) vw[t] *= inv;
        }
        for (int i = tid; i < MV; i += 1024) g_wv[i] = 0.f;
        __syncthreads();
        if (tid < 31 * 20) {
            int t = tid / 20, l = tid % 20;
            int c = med[t * 20 + l];
            bool dup = false;
            for (int l2 = 0; l2 < l; l2++)
                if (med[t * 20 + l2] == c) dup = true;
            if (!dup) atomicAdd(&g_wv[c], vw[t]);
        }
    }
}

// ---------------- launch ----------------
extern "C" void kernel_launch(void* const* d_in, const int* in_sizes, int n_in,
                              void* d_out, int out_size) {
    const int*   diag_codes = (const int*)d_in[0];
    const int*   proc_codes = (const int*)d_in[1];
    const int*   med_codes  = (const int*)d_in[2];
    const float* diag_emb   = (const float*)d_in[3];
    const float* proc_emb   = (const float*)d_in[4];
    const float* gd_wih     = (const float*)d_in[5];
    const float* gd_whh     = (const float*)d_in[6];
    const float* gd_bih     = (const float*)d_in[7];
    const float* gd_bhh     = (const float*)d_in[8];
    const float* gp_wih     = (const float*)d_in[9];
    const float* gp_whh     = (const float*)d_in[10];
    const float* gp_bih     = (const float*)d_in[11];
    const float* gp_bhh     = (const float*)d_in[12];
    const float* q_w        = (const float*)d_in[13];
    const float* q_b        = (const float*)d_in[14];
    const float* adj_ehr    = (const float*)d_in[15];
    const float* adj_ddi    = (const float*)d_in[16];
    const float* w1_ehr     = (const float*)d_in[17];
    const float* b1_ehr     = (const float*)d_in[18];
    const float* w2_ehr     = (const float*)d_in[19];
    const float* b2_ehr     = (const float*)d_in[20];
    const float* w1_ddi     = (const float*)d_in[21];
    const float* b1_ddi     = (const float*)d_in[22];
    const float* w2_ddi     = (const float*)d_in[23];
    const float* b2_ddi     = (const float*)d_in[24];
    const float* inter      = (const float*)d_in[25];
    const float* proj_w     = (const float*)d_in[26];
    const float* proj_b     = (const float*)d_in[27];
    float* out = (float*)d_out;

    // 1: embed + input gates
    k_gie<<<64, 256>>>(diag_codes, proc_codes, diag_emb, proc_emb,
                       gd_wih, gp_wih, gd_bih, gp_bih);
    // 2: GRU clusters + CSR + SpMM-0 + prep
    k_fused<<<16 + 2 * MV, 256>>>(gd_whh, gp_whh, gd_bhh, gp_bhh,
                                  adj_ehr, adj_ddi, w1_ehr, w1_ddi,
                                  b1_ehr, b1_ddi, inter, b2_ehr, b2_ddi);
    // 3: SpMM-1 + queries (+ wemb zero)
    k_sq<<<2 * MV + 128, 256>>>(q_w, q_b);
    // 4: prior + fused logits
    k_mm2<0><<<dim3(4, 64), 256>>>(w2_ehr, w2_ddi, nullptr, nullptr);
    // 5: softmax + visit attention
    k_tail<<<2, 1024>>>(med_codes);
    // 6: output projection (second half of proj_w = +H*H)
    k_mm2<1><<<dim3(4, 64), 256>>>(proj_w, proj_w + H * H, proj_b, out);
}